// round 10
// baseline (speedup 1.0000x reference)
#include <cuda_runtime.h>
#include <cuda_fp16.h>
#include <mma.h>
#include <math.h>

using namespace nvcuda;

// Problem-fixed capacities (dataset constants)
#define NCAP 100000
#define NPAD (NCAP + 128)
#define ECAP 1600000
#define ITERS 5

struct __align__(8) EdgeRec { int src; float w; };
typedef unsigned long long u64;
typedef unsigned int u32;

// ---- static device scratch (no allocation allowed) ----
// zero region: [counts | cursor | total]
__device__ int     g_zero[2 * NCAP + 4];
__device__ int     g_rowoff[NCAP];
__device__ int     g_rowend[NCAP];
__device__ float   g_dis[NCAP];
__device__ EdgeRec g_edges[ECAP];
__device__ float   g_aggx[NCAP * 3];
__device__ float4  g_t[NCAP * 16];
__device__ float4  g_u[NCAP * 16];
__device__ float4  g_v[NCAP * 16];
// fp16 mirrors, padded (64 halfs = 8 uint4 per node)
__device__ uint4   g_t16[NPAD * 8];
__device__ uint4   g_u16[NPAD * 8];
__device__ uint4   g_v16[NPAD * 8];
// fp16 weights: Wr_t, W11, W12, W21, W22 (each 64x64)
__device__ uint4   g_w16[5 * 4096 / 8];

// ---- fp16 pack/unpack ----
__device__ __forceinline__ float2 h2f(u32 q) {
    __half2 h = *reinterpret_cast<__half2*>(&q);
    return __half22float2(h);
}
__device__ __forceinline__ u32 f2h(float x, float y) {
    __half2 h = __floats2half2_rn(x, y);
    return *reinterpret_cast<u32*>(&h);
}

// =============== graph setup kernels ===============

__global__ void k_count(const int* __restrict__ dst, int E, int* __restrict__ counts) {
    int i = blockIdx.x * blockDim.x + threadIdx.x;
    if (i < E) atomicAdd(&counts[dst[i]], 1);
}

// merged: dis + CSR segment alloc + fp16 weight conversion
__global__ void k_setup2(const int* __restrict__ counts, float* __restrict__ dis,
                         int* __restrict__ rowoff, int* __restrict__ rowend,
                         int* __restrict__ total, int N,
                         const float* __restrict__ Wr, const float* __restrict__ W11,
                         const float* __restrict__ W12, const float* __restrict__ W21,
                         const float* __restrict__ W22, __half* __restrict__ w16) {
    int i = blockIdx.x * blockDim.x + threadIdx.x;
    if (i < 4096) {
        w16[i]            = __float2half_rn(Wr[i]);
        w16[4096 + i]     = __float2half_rn(W11[i]);
        w16[2 * 4096 + i] = __float2half_rn(W12[i]);
        w16[3 * 4096 + i] = __float2half_rn(W21[i]);
        w16[4 * 4096 + i] = __float2half_rn(W22[i]);
    }
    if (i < N) {
        int c = counts[i];
        dis[i] = rsqrtf((float)(c + 1));
        int off = atomicAdd(total, c);
        rowoff[i] = off;
        rowend[i] = off + c;
    }
}

__global__ void k_fill(const int* __restrict__ srcA, const int* __restrict__ dstA, int E,
                       const int* __restrict__ rowoff, int* __restrict__ cursor,
                       const float* __restrict__ dis, EdgeRec* __restrict__ edges) {
    int i = blockIdx.x * blockDim.x + threadIdx.x;
    if (i >= E) return;
    int s = srcA[i], d = dstA[i];
    int pos = rowoff[d] + atomicAdd(&cursor[d], 1);
    EdgeRec r;
    r.src = s;
    r.w = dis[s] * dis[d];
    edges[pos] = r;
}

// fused: aggx = agg(x) (warp per node, lanes split edges) + projection
// t = relu(aggx @ Wp + bp), fp32 + fp16 mirror
__global__ void k_aggx_proj(const float* __restrict__ x, const EdgeRec* __restrict__ edges,
                            const int* __restrict__ rowoff, const int* __restrict__ rowend,
                            const float* __restrict__ dis,
                            const float* __restrict__ Wp, const float* __restrict__ bp,
                            float* __restrict__ aggx, float* __restrict__ t,
                            __half* __restrict__ t16, int N) {
    int node = blockIdx.x * 8 + (threadIdx.x >> 5);
    int lane = threadIdx.x & 31;
    if (node >= N) return;
    float a0 = 0.f, a1 = 0.f, a2 = 0.f;
    int e0 = rowoff[node], e1 = rowend[node];
    for (int e = e0 + lane; e < e1; e += 32) {
        EdgeRec r = edges[e];
        const float* xp = x + (size_t)r.src * 3;
        a0 = fmaf(r.w, __ldg(xp), a0);
        a1 = fmaf(r.w, __ldg(xp + 1), a1);
        a2 = fmaf(r.w, __ldg(xp + 2), a2);
    }
    if (lane == 0) {
        float dv = dis[node];
        float sw = dv * dv;
        const float* xp = x + (size_t)node * 3;
        a0 = fmaf(sw, xp[0], a0);
        a1 = fmaf(sw, xp[1], a1);
        a2 = fmaf(sw, xp[2], a2);
    }
#pragma unroll
    for (int off = 16; off > 0; off >>= 1) {
        a0 += __shfl_xor_sync(0xffffffffu, a0, off);
        a1 += __shfl_xor_sync(0xffffffffu, a1, off);
        a2 += __shfl_xor_sync(0xffffffffu, a2, off);
    }
    if (lane == 0) {
        aggx[node * 3] = a0;
        aggx[node * 3 + 1] = a1;
        aggx[node * 3 + 2] = a2;
    }
    // projection: lane covers cols 2*lane, 2*lane+1
#pragma unroll
    for (int jj = 0; jj < 2; jj++) {
        int j = 2 * lane + jj;
        float acc = bp[j];
        acc = fmaf(a0, Wp[j], acc);
        acc = fmaf(a1, Wp[64 + j], acc);
        acc = fmaf(a2, Wp[128 + j], acc);
        acc = fmaxf(acc, 0.f);
        t[(size_t)node * 64 + j] = acc;
        t16[(size_t)node * 64 + j] = __float2half_rn(acc);
    }
}

// =============== main aggregation: quarter-warp gather ===============
// 4 nodes per warp, 8 lanes per node, uint4 (16B) per lane -> one 128B row
// per feature-LDG *warp instruction* covers 4 edges / 4 L2 lines.
template <int RELU, int RES, int W32>
__global__ void __launch_bounds__(256) k_aggq(
    const uint4* __restrict__ U16, const EdgeRec* __restrict__ edges,
    const int* __restrict__ rowoff, const int* __restrict__ rowend,
    const float* __restrict__ dis,
    const float* __restrict__ bias, const float* __restrict__ res,
    float* __restrict__ out, uint4* __restrict__ out16, int N) {
    int tid = threadIdx.x;
    int sub = tid & 7;                 // lane within node group
    int node = blockIdx.x * 32 + (tid >> 3);
    if (node >= N) return;

    float ac0[8], ac1[8], ac2[8], ac3[8];
#pragma unroll
    for (int j = 0; j < 8; j++) { ac0[j] = 0.f; ac1[j] = 0.f; ac2[j] = 0.f; ac3[j] = 0.f; }

    int e = rowoff[node];
    int e1 = rowend[node];
    for (; e + 4 <= e1; e += 4) {
        u64 er0 = *(const u64*)(edges + e);
        u64 er1 = *(const u64*)(edges + e + 1);
        u64 er2 = *(const u64*)(edges + e + 2);
        u64 er3 = *(const u64*)(edges + e + 3);
        int s0 = (int)(u32)er0; float w0 = __uint_as_float((u32)(er0 >> 32));
        int s1 = (int)(u32)er1; float w1 = __uint_as_float((u32)(er1 >> 32));
        int s2 = (int)(u32)er2; float w2 = __uint_as_float((u32)(er2 >> 32));
        int s3 = (int)(u32)er3; float w3 = __uint_as_float((u32)(er3 >> 32));
        uint4 q0 = U16[(size_t)s0 * 8 + sub];
        uint4 q1 = U16[(size_t)s1 * 8 + sub];
        uint4 q2 = U16[(size_t)s2 * 8 + sub];
        uint4 q3 = U16[(size_t)s3 * 8 + sub];
        {
            float2 fa = h2f(q0.x), fb = h2f(q0.y), fc = h2f(q0.z), fd = h2f(q0.w);
            ac0[0] = fmaf(w0, fa.x, ac0[0]); ac0[1] = fmaf(w0, fa.y, ac0[1]);
            ac0[2] = fmaf(w0, fb.x, ac0[2]); ac0[3] = fmaf(w0, fb.y, ac0[3]);
            ac0[4] = fmaf(w0, fc.x, ac0[4]); ac0[5] = fmaf(w0, fc.y, ac0[5]);
            ac0[6] = fmaf(w0, fd.x, ac0[6]); ac0[7] = fmaf(w0, fd.y, ac0[7]);
        }
        {
            float2 fa = h2f(q1.x), fb = h2f(q1.y), fc = h2f(q1.z), fd = h2f(q1.w);
            ac1[0] = fmaf(w1, fa.x, ac1[0]); ac1[1] = fmaf(w1, fa.y, ac1[1]);
            ac1[2] = fmaf(w1, fb.x, ac1[2]); ac1[3] = fmaf(w1, fb.y, ac1[3]);
            ac1[4] = fmaf(w1, fc.x, ac1[4]); ac1[5] = fmaf(w1, fc.y, ac1[5]);
            ac1[6] = fmaf(w1, fd.x, ac1[6]); ac1[7] = fmaf(w1, fd.y, ac1[7]);
        }
        {
            float2 fa = h2f(q2.x), fb = h2f(q2.y), fc = h2f(q2.z), fd = h2f(q2.w);
            ac2[0] = fmaf(w2, fa.x, ac2[0]); ac2[1] = fmaf(w2, fa.y, ac2[1]);
            ac2[2] = fmaf(w2, fb.x, ac2[2]); ac2[3] = fmaf(w2, fb.y, ac2[3]);
            ac2[4] = fmaf(w2, fc.x, ac2[4]); ac2[5] = fmaf(w2, fc.y, ac2[5]);
            ac2[6] = fmaf(w2, fd.x, ac2[6]); ac2[7] = fmaf(w2, fd.y, ac2[7]);
        }
        {
            float2 fa = h2f(q3.x), fb = h2f(q3.y), fc = h2f(q3.z), fd = h2f(q3.w);
            ac3[0] = fmaf(w3, fa.x, ac3[0]); ac3[1] = fmaf(w3, fa.y, ac3[1]);
            ac3[2] = fmaf(w3, fb.x, ac3[2]); ac3[3] = fmaf(w3, fb.y, ac3[3]);
            ac3[4] = fmaf(w3, fc.x, ac3[4]); ac3[5] = fmaf(w3, fc.y, ac3[5]);
            ac3[6] = fmaf(w3, fd.x, ac3[6]); ac3[7] = fmaf(w3, fd.y, ac3[7]);
        }
    }
    for (; e < e1; e++) {
        u64 er = *(const u64*)(edges + e);
        int s = (int)(u32)er; float w = __uint_as_float((u32)(er >> 32));
        uint4 q = U16[(size_t)s * 8 + sub];
        float2 fa = h2f(q.x), fb = h2f(q.y), fc = h2f(q.z), fd = h2f(q.w);
        ac0[0] = fmaf(w, fa.x, ac0[0]); ac0[1] = fmaf(w, fa.y, ac0[1]);
        ac0[2] = fmaf(w, fb.x, ac0[2]); ac0[3] = fmaf(w, fb.y, ac0[3]);
        ac0[4] = fmaf(w, fc.x, ac0[4]); ac0[5] = fmaf(w, fc.y, ac0[5]);
        ac0[6] = fmaf(w, fd.x, ac0[6]); ac0[7] = fmaf(w, fd.y, ac0[7]);
    }
    // self loop
    {
        float dv = dis[node];
        float sw = dv * dv;
        uint4 q = U16[(size_t)node * 8 + sub];
        float2 fa = h2f(q.x), fb = h2f(q.y), fc = h2f(q.z), fd = h2f(q.w);
        ac1[0] = fmaf(sw, fa.x, ac1[0]); ac1[1] = fmaf(sw, fa.y, ac1[1]);
        ac1[2] = fmaf(sw, fb.x, ac1[2]); ac1[3] = fmaf(sw, fb.y, ac1[3]);
        ac1[4] = fmaf(sw, fc.x, ac1[4]); ac1[5] = fmaf(sw, fc.y, ac1[5]);
        ac1[6] = fmaf(sw, fd.x, ac1[6]); ac1[7] = fmaf(sw, fd.y, ac1[7]);
    }
    float o[8];
#pragma unroll
    for (int j = 0; j < 8; j++) o[j] = (ac0[j] + ac1[j]) + (ac2[j] + ac3[j]);
    if (bias) {
        float4 b0 = ((const float4*)bias)[sub * 2];
        float4 b1 = ((const float4*)bias)[sub * 2 + 1];
        o[0] += b0.x; o[1] += b0.y; o[2] += b0.z; o[3] += b0.w;
        o[4] += b1.x; o[5] += b1.y; o[6] += b1.z; o[7] += b1.w;
    }
    if (RES) {
        float4 r0 = ((const float4*)res)[(size_t)node * 16 + sub * 2];
        float4 r1 = ((const float4*)res)[(size_t)node * 16 + sub * 2 + 1];
        o[0] += r0.x; o[1] += r0.y; o[2] += r0.z; o[3] += r0.w;
        o[4] += r1.x; o[5] += r1.y; o[6] += r1.z; o[7] += r1.w;
    }
    if (RELU) {
#pragma unroll
        for (int j = 0; j < 8; j++) o[j] = fmaxf(o[j], 0.f);
    }
    if (W32) {
        ((float4*)out)[(size_t)node * 16 + sub * 2] =
            make_float4(o[0], o[1], o[2], o[3]);
        ((float4*)out)[(size_t)node * 16 + sub * 2 + 1] =
            make_float4(o[4], o[5], o[6], o[7]);
    }
    {
        uint4 m;
        m.x = f2h(o[0], o[1]);
        m.y = f2h(o[2], o[3]);
        m.z = f2h(o[4], o[5]);
        m.w = f2h(o[6], o[7]);
        out16[(size_t)node * 8 + sub] = m;
    }
}

// =============== head aggregation kernels ===============

__global__ void k_agg32(const float* __restrict__ u, const EdgeRec* __restrict__ edges,
                        const int* __restrict__ rowoff, const int* __restrict__ rowend,
                        const float* __restrict__ dis,
                        const float* __restrict__ bias, int relu,
                        float* __restrict__ out, int N) {
    int node = blockIdx.x * 8 + (threadIdx.x >> 5);
    int lane = threadIdx.x & 31;
    if (node >= N) return;
    float acc = 0.f;
    int e0 = rowoff[node], e1 = rowend[node];
    for (int e = e0; e < e1; e++) {
        EdgeRec r = edges[e];
        acc = fmaf(r.w, u[(size_t)r.src * 32 + lane], acc);
    }
    float dv = dis[node];
    acc = fmaf(dv * dv, u[(size_t)node * 32 + lane], acc);
    if (bias) acc += bias[lane];
    if (relu) acc = fmaxf(acc, 0.f);
    out[(size_t)node * 32 + lane] = acc;
}

template <int W>
__global__ void k_agg_t(const float* __restrict__ u, const EdgeRec* __restrict__ edges,
                        const int* __restrict__ rowoff, const int* __restrict__ rowend,
                        const float* __restrict__ dis,
                        const float* __restrict__ bias, int relu,
                        float* __restrict__ out, int N) {
    int node = blockIdx.x * blockDim.x + threadIdx.x;
    if (node >= N) return;
    float acc[W];
#pragma unroll
    for (int k = 0; k < W; k++) acc[k] = 0.f;
    int e0 = rowoff[node], e1 = rowend[node];
    for (int e = e0; e < e1; e++) {
        EdgeRec r = edges[e];
        const float* up = u + (size_t)r.src * W;
#pragma unroll
        for (int k = 0; k < W; k++) acc[k] = fmaf(r.w, __ldg(up + k), acc[k]);
    }
    float dv = dis[node];
    float sw = dv * dv;
    const float* us = u + (size_t)node * W;
#pragma unroll
    for (int k = 0; k < W; k++) acc[k] = fmaf(sw, us[k], acc[k]);
    if (bias) {
#pragma unroll
        for (int k = 0; k < W; k++) acc[k] += bias[k];
    }
    if (relu) {
#pragma unroll
        for (int k = 0; k < W; k++) acc[k] = fmaxf(acc[k], 0.f);
    }
#pragma unroll
    for (int k = 0; k < W; k++) out[(size_t)node * W + k] = acc[k];
}

// =============== dense kernels ===============

// tensor-core matmul: C[N,64] = A16[N,64] @ W16[64,64]  (fp16 in, fp32 acc)
template <int RECALL>
__global__ void __launch_bounds__(256) k_mmTC(
    const __half* __restrict__ A16, const __half* __restrict__ W16,
    const float* __restrict__ Wx, const float* __restrict__ brv,
    const float* __restrict__ aggx,
    float* __restrict__ out32, __half* __restrict__ out16, int N) {
    __shared__ __align__(32) __half Ws[64 * 64];
    __shared__ __align__(32) float stage[128 * 64];
    int tid = threadIdx.x;
    int warp = tid >> 5;
    int row0 = blockIdx.x * 128;

    {
        const uint4* src = (const uint4*)W16;
        uint4* dst = (uint4*)Ws;
        for (int i = tid; i < 512; i += 256) dst[i] = src[i];
    }
    __syncthreads();

    wmma::fragment<wmma::accumulator, 16, 16, 16, float> acc[4];
#pragma unroll
    for (int nt = 0; nt < 4; nt++) wmma::fill_fragment(acc[nt], 0.f);

    const __half* Abase = A16 + (size_t)(row0 + warp * 16) * 64;
#pragma unroll
    for (int kt = 0; kt < 4; kt++) {
        wmma::fragment<wmma::matrix_a, 16, 16, 16, __half, wmma::row_major> af;
        wmma::load_matrix_sync(af, Abase + kt * 16, 64);
#pragma unroll
        for (int nt = 0; nt < 4; nt++) {
            wmma::fragment<wmma::matrix_b, 16, 16, 16, __half, wmma::row_major> bf;
            wmma::load_matrix_sync(bf, Ws + kt * 16 * 64 + nt * 16, 64);
            wmma::mma_sync(acc[nt], af, bf, acc[nt]);
        }
    }
#pragma unroll
    for (int nt = 0; nt < 4; nt++)
        wmma::store_matrix_sync(stage + warp * 16 * 64 + nt * 16, acc[nt], 64,
                                wmma::mem_row_major);
    __syncthreads();

    for (int i = tid; i < 128 * 16; i += 256) {
        int row = i >> 4;
        int q = i & 15;
        int grow = row0 + row;
        if (grow >= N) break;
        float4 c = ((const float4*)stage)[i];
        if (RECALL) {
            float a0 = aggx[grow * 3], a1 = aggx[grow * 3 + 1], a2 = aggx[grow * 3 + 2];
            int col = q * 4;
#pragma unroll
            for (int jj = 0; jj < 4; jj++) {
                float add = fmaf(a0, Wx[col + jj],
                             fmaf(a1, Wx[64 + col + jj],
                              fmaf(a2, Wx[128 + col + jj], brv[col + jj])));
                (&c.x)[jj] += add;
            }
            ((float4*)out32)[(size_t)grow * 16 + q] = c;
        }
        uint2 m;
        m.x = f2h(c.x, c.y);
        m.y = f2h(c.z, c.w);
        ((uint2*)out16)[(size_t)grow * 16 + q] = m;
    }
}

// small head matmuls: warp per node
template <int FIN, int FOUT>
__global__ void k_mm_small(const float* __restrict__ A, const float* __restrict__ W,
                           float* __restrict__ C, int N) {
    __shared__ float Ws[FIN * FOUT + 32];
    int tid = threadIdx.x;
    for (int i = tid; i < FIN * FOUT; i += blockDim.x) Ws[i] = W[i];
    for (int i = FIN * FOUT + tid; i < FIN * FOUT + 32; i += blockDim.x) Ws[i] = 0.f;
    __syncthreads();
    int node = blockIdx.x * 4 + (tid >> 5);
    int j = tid & 31;
    if (node >= N) return;
    float acc = 0.f;
    const float* a = A + (size_t)node * FIN;
#pragma unroll
    for (int k = 0; k < FIN; k++) {
        float av = __ldg(a + k);
        acc = fmaf(av, Ws[k * FOUT + j], acc);
    }
    if (j < FOUT) C[(size_t)node * FOUT + j] = acc;
}

// =============== host launch ===============

extern "C" void kernel_launch(void* const* d_in, const int* in_sizes, int n_in,
                              void* d_out, int out_size) {
    const float* x   = (const float*)d_in[0];
    const float* Wp  = (const float*)d_in[1];
    const float* bp  = (const float*)d_in[2];
    const float* Wr  = (const float*)d_in[3];
    const float* br  = (const float*)d_in[4];
    const float* W11 = (const float*)d_in[5];
    const float* b11 = (const float*)d_in[6];
    const float* W12 = (const float*)d_in[7];
    const float* b12 = (const float*)d_in[8];
    const float* W21 = (const float*)d_in[9];
    const float* b21 = (const float*)d_in[10];
    const float* W22 = (const float*)d_in[11];
    const float* b22 = (const float*)d_in[12];
    const float* Wh1 = (const float*)d_in[13];
    const float* bh1 = (const float*)d_in[14];
    const float* Wh2 = (const float*)d_in[15];
    const float* bh2 = (const float*)d_in[16];
    const float* Wh3 = (const float*)d_in[17];
    const float* bh3 = (const float*)d_in[18];
    const int*   ei  = (const int*)d_in[19];

    int N = in_sizes[0] / 3;
    int E = in_sizes[19] / 2;
    const int* esrc = ei;
    const int* edst = ei + E;

    int *zero, *rowoff, *rowend;
    float *dis, *aggx;
    EdgeRec* edges;
    float4 *t4, *u4, *v4;
    uint4 *t16p, *u16p, *v16p, *w16p;
    cudaGetSymbolAddress((void**)&zero, g_zero);
    cudaGetSymbolAddress((void**)&rowoff, g_rowoff);
    cudaGetSymbolAddress((void**)&rowend, g_rowend);
    cudaGetSymbolAddress((void**)&dis, g_dis);
    cudaGetSymbolAddress((void**)&edges, g_edges);
    cudaGetSymbolAddress((void**)&aggx, g_aggx);
    cudaGetSymbolAddress((void**)&t4, g_t);
    cudaGetSymbolAddress((void**)&u4, g_u);
    cudaGetSymbolAddress((void**)&v4, g_v);
    cudaGetSymbolAddress((void**)&t16p, g_t16);
    cudaGetSymbolAddress((void**)&u16p, g_u16);
    cudaGetSymbolAddress((void**)&v16p, g_v16);
    cudaGetSymbolAddress((void**)&w16p, g_w16);
    int* counts = zero;
    int* cursor = zero + NCAP;
    int* total  = zero + 2 * NCAP;
    float* t = (float*)t4;
    float* u = (float*)u4;
    float* v = (float*)v4;
    __half* t16 = (__half*)t16p;
    __half* u16 = (__half*)u16p;
    __half* v16 = (__half*)v16p;
    __half* w16 = (__half*)w16p;
    __half* Wr16   = w16;
    __half* W11_16 = w16 + 4096;
    __half* W12_16 = w16 + 2 * 4096;
    __half* W21_16 = w16 + 3 * 4096;
    __half* W22_16 = w16 + 4 * 4096;

    int nbE = (E + 255) / 256;
    int nbN = (N + 255) / 256;
    int nbWarp = (N + 7) / 8;       // 8 nodes per 256-thread block
    int nbAgg = (N + 31) / 32;      // 32 nodes per 256-thread block (quarter-warp)
    int nbTC = (N + 127) / 128;     // tensor-core mm tiles
    int nbW4 = (N + 3) / 4;

    // ---- graph setup: exactly 5 launches before the first loop kernel ----
    cudaMemsetAsync(zero, 0, (size_t)(2 * NCAP + 4) * sizeof(int), 0);   // #1
    k_count<<<nbE, 256>>>(edst, E, counts);                               // #2
    k_setup2<<<nbN, 256>>>(counts, dis, rowoff, rowend, total, N,
                           Wr, W11, W12, W21, W22, w16);                  // #3
    k_fill<<<nbE, 256>>>(esrc, edst, E, rowoff, cursor, dis, edges);      // #4
    k_aggx_proj<<<nbWarp, 256>>>(x, edges, rowoff, rowend, dis,
                                 Wp, bp, aggx, t, t16, N);                // #5

    const float* Wrx = Wr + 64 * 64;  // rows 64..66 of Wr (x part)

    // ---- iterations ----
    for (int it = 0; it < ITERS; it++) {
        // recall: v16 = agg(t16); t,t16 = v16@Wr_t + aggx@Wr_x + br
        k_aggq<0, 0, 0><<<nbAgg, 256>>>(t16p, edges, rowoff, rowend, dis,
                                        nullptr, nullptr, nullptr, v16p, N);
        k_mmTC<1><<<nbTC, 256>>>(v16, Wr16, Wrx, br, aggx, t, t16, N);
        // block 1
        k_mmTC<0><<<nbTC, 256>>>(t16, W11_16, nullptr, nullptr, nullptr,
                                 nullptr, u16, N);
        k_aggq<1, 0, 0><<<nbAgg, 256>>>(u16p, edges, rowoff, rowend, dis,
                                        b11, nullptr, nullptr, v16p, N);
        k_mmTC<0><<<nbTC, 256>>>(v16, W12_16, nullptr, nullptr, nullptr,
                                 nullptr, u16, N);
        k_aggq<1, 1, 1><<<nbAgg, 256>>>(u16p, edges, rowoff, rowend, dis,
                                        b12, t, t, t16p, N);
        // block 2
        k_mmTC<0><<<nbTC, 256>>>(t16, W21_16, nullptr, nullptr, nullptr,
                                 nullptr, u16, N);
        k_aggq<1, 0, 0><<<nbAgg, 256>>>(u16p, edges, rowoff, rowend, dis,
                                        b21, nullptr, nullptr, v16p, N);
        k_mmTC<0><<<nbTC, 256>>>(v16, W22_16, nullptr, nullptr, nullptr,
                                 nullptr, u16, N);
        k_aggq<1, 1, 1><<<nbAgg, 256>>>(u16p, edges, rowoff, rowend, dis,
                                        b22, t, t, t16p, N);
    }

    // ---- head (fp32 throughout) ----
    k_mm_small<64, 32><<<nbW4, 128>>>(t, Wh1, u, N);
    k_agg32<<<nbWarp, 256>>>(u, edges, rowoff, rowend, dis, bh1, 1, v, N);
    k_mm_small<32, 8><<<nbW4, 128>>>(v, Wh2, u, N);
    k_agg_t<8><<<nbN, 256>>>(u, edges, rowoff, rowend, dis, bh2, 1, v, N);
    k_mm_small<8, 2><<<nbW4, 128>>>(v, Wh3, u, N);
    k_agg_t<2><<<nbN, 256>>>(u, edges, rowoff, rowend, dis, bh3, 0, (float*)d_out, N);
}